// round 1
// baseline (speedup 1.0000x reference)
#include <cuda_runtime.h>

#define NPTS   65536     // B*T
#define TPB    128

__global__ __launch_bounds__(TPB)
void decoder_fused_kernel(
    const float* __restrict__ p,      // [16,4096,3]
    const float* __restrict__ c,      // [16,4,128,128,32]
    const float* __restrict__ Cmat,   // [16,4,4,3]
    const float* __restrict__ fcpW,   // [3,32]
    const float* __restrict__ fcpb,   // [32]
    const float* __restrict__ W0,     // [5,32,32]
    const float* __restrict__ b0,     // [5,32]
    const float* __restrict__ W1,     // [5,32,32]
    const float* __restrict__ b1,     // [5,32]
    const float* __restrict__ Wout,   // [32,1]
    const float* __restrict__ bout,   // [1]
    float* __restrict__ out)          // [16,4096]
{
    __shared__ __align__(16) float sW0[5 * 1024];
    __shared__ __align__(16) float sW1[5 * 1024];
    __shared__ __align__(16) float sb0[5 * 32];
    __shared__ __align__(16) float sb1[5 * 32];
    __shared__ __align__(16) float sWp[96];
    __shared__ __align__(16) float sbp[32];
    __shared__ __align__(16) float sWo[32];
    __shared__ float sbo;
    __shared__ float sC[4][8];   // per view: c00,c01,c02,c10,c11,c12,den

    const int tid = threadIdx.x;
    const int pt  = blockIdx.x * TPB + tid;
    const int b   = pt >> 12;            // 4096 points per batch; block never spans two b

    // ---- stage weights in shared (warp-uniform reads later -> LDS broadcast) ----
    for (int i = tid; i < 5120; i += TPB) { sW0[i] = W0[i]; sW1[i] = W1[i]; }
    for (int i = tid; i < 160;  i += TPB) { sb0[i] = b0[i]; sb1[i] = b1[i]; }
    if (tid < 96) sWp[tid] = fcpW[tid];
    if (tid < 32) { sbp[tid] = fcpb[tid]; sWo[tid] = Wout[tid]; }
    if (tid == 0) sbo = bout[0];
    if (tid < 28) {
        int l = tid / 7, k = tid % 7;
        const float* Cb = Cmat + (b * 4 + l) * 12;   // [4,3] per (b,l)
        float v;
        if (k < 6) v = Cb[k];                 // rows 0,1 (i=0: idx0..2, i=1: idx3..5)
        else       v = Cb[9] + 0.05f;         // row 3, col 0 -> denominator
        sC[l][k] = v;
    }
    __syncthreads();

    // ---- load point ----
    const float pr0 = p[pt * 3 + 0];
    const float pr1 = p[pt * 3 + 1];
    const float pr2 = p[pt * 3 + 2];
    const float ps0 = pr0 / 0.55f;
    const float ps1 = pr1 / 0.55f;
    const float ps2 = pr2 / 0.55f;

    // ---- bilinear gather over 4 views -> cf[32] ----
    float cf[32];
    #pragma unroll
    for (int j = 0; j < 32; j++) cf[j] = 0.0f;

    const float interval = 2.0f / 127.0f;

    #pragma unroll
    for (int l = 0; l < 4; l++) {
        const float c00 = sC[l][0], c01 = sC[l][1], c02 = sC[l][2];
        const float c10 = sC[l][3], c11 = sC[l][4], c12 = sC[l][5];
        const float den = sC[l][6];

        float px = (c00 * ps0 + c01 * ps1 + c02 * ps2) / den;
        float py = (c10 * ps0 + c11 * ps1 + c12 * ps2) / den;

        float xg = (px + 1.0f) / interval;
        float yg = (py + 1.0f) / interval;
        // match ref: first >=127 -> 126.9, then <0 -> 0
        xg = (xg >= 127.0f) ? 126.9f : xg;  xg = (xg < 0.0f) ? 0.0f : xg;
        yg = (yg >= 127.0f) ? 126.9f : yg;  yg = (yg < 0.0f) ? 0.0f : yg;

        // half-to-even rounding, same as jnp.round
        const float xl = rintf(xg - 0.5f), xr = rintf(xg + 0.5f);
        const float yl = rintf(yg - 0.5f), yh = rintf(yg + 0.5f);
        const int xil = (int)xl, xir = (int)xr;
        const int yil = (int)yl, yih = (int)yh;

        const float dx = xr - xg, dy = yh - yg;
        const float w11 = dx * dy;
        const float w12 = (1.0f - dx) * dy;
        const float w21 = dx * (1.0f - dy);
        const float w22 = (1.0f - dx) * (1.0f - dy);

        const int base = (b * 4 + l) * 128 * 128;     // plane index (rows of 32 floats)
        const float4* r11 = (const float4*)(c + (size_t)(base + xil * 128 + yil) * 32);
        const float4* r12 = (const float4*)(c + (size_t)(base + xir * 128 + yil) * 32);
        const float4* r21 = (const float4*)(c + (size_t)(base + xil * 128 + yih) * 32);
        const float4* r22 = (const float4*)(c + (size_t)(base + xir * 128 + yih) * 32);

        #pragma unroll
        for (int q = 0; q < 8; q++) {
            const float4 a = __ldg(r11 + q);
            const float4 e = __ldg(r12 + q);
            const float4 f = __ldg(r21 + q);
            const float4 g = __ldg(r22 + q);
            cf[4*q + 0] += w11 * a.x + w12 * e.x + w21 * f.x + w22 * g.x;
            cf[4*q + 1] += w11 * a.y + w12 * e.y + w21 * f.y + w22 * g.y;
            cf[4*q + 2] += w11 * a.z + w12 * e.z + w21 * f.z + w22 * g.z;
            cf[4*q + 3] += w11 * a.w + w12 * e.w + w21 * f.w + w22 * g.w;
        }
    }

    // ---- fc_p + first cf add ----
    float x[32];
    #pragma unroll
    for (int j = 0; j < 32; j++) {
        float v = sbp[j];
        v = fmaf(pr0, sWp[j],      v);
        v = fmaf(pr1, sWp[32 + j], v);
        v = fmaf(pr2, sWp[64 + j], v);
        x[j] = v + cf[j];
    }

    // ---- 5 resnet blocks ----
    #pragma unroll 1
    for (int blk = 0; blk < 5; blk++) {
        if (blk > 0) {
            #pragma unroll
            for (int j = 0; j < 32; j++) x[j] += cf[j];
        }
        const float* w0  = sW0 + blk * 1024;
        const float* bb0 = sb0 + blk * 32;
        const float* w1  = sW1 + blk * 1024;
        const float* bb1 = sb1 + blk * 32;

        // h = relu(x) @ W0 + b0
        float h[32];
        #pragma unroll
        for (int j = 0; j < 32; j++) h[j] = bb0[j];
        #pragma unroll 4
        for (int k = 0; k < 32; k++) {
            const float xr = fmaxf(x[k], 0.0f);
            const float4* wr = (const float4*)(w0 + k * 32);
            #pragma unroll
            for (int q = 0; q < 8; q++) {
                const float4 w = wr[q];
                h[4*q + 0] = fmaf(xr, w.x, h[4*q + 0]);
                h[4*q + 1] = fmaf(xr, w.y, h[4*q + 1]);
                h[4*q + 2] = fmaf(xr, w.z, h[4*q + 2]);
                h[4*q + 3] = fmaf(xr, w.w, h[4*q + 3]);
            }
        }

        // x += relu(h) @ W1 + b1   (accumulate residual directly into x)
        #pragma unroll
        for (int j = 0; j < 32; j++) x[j] += bb1[j];
        #pragma unroll 4
        for (int k = 0; k < 32; k++) {
            const float hr = fmaxf(h[k], 0.0f);
            const float4* wr = (const float4*)(w1 + k * 32);
            #pragma unroll
            for (int q = 0; q < 8; q++) {
                const float4 w = wr[q];
                x[4*q + 0] = fmaf(hr, w.x, x[4*q + 0]);
                x[4*q + 1] = fmaf(hr, w.y, x[4*q + 1]);
                x[4*q + 2] = fmaf(hr, w.z, x[4*q + 2]);
                x[4*q + 3] = fmaf(hr, w.w, x[4*q + 3]);
            }
        }
    }

    // ---- output head ----
    float acc = sbo;
    #pragma unroll
    for (int k = 0; k < 32; k++)
        acc = fmaf(fmaxf(x[k], 0.0f), sWo[k], acc);
    out[pt] = acc;
}

extern "C" void kernel_launch(void* const* d_in, const int* in_sizes, int n_in,
                              void* d_out, int out_size)
{
    // metadata order: p, z, c, C_mat, fc_p_W, fc_p_b,
    //                 blocks_W0, blocks_b0, blocks_W1, blocks_b1, fc_out_W, fc_out_b
    const float* p    = (const float*)d_in[0];
    // d_in[1] = z (unused by the reference graph)
    const float* c    = (const float*)d_in[2];
    const float* Cm   = (const float*)d_in[3];
    const float* fpW  = (const float*)d_in[4];
    const float* fpb  = (const float*)d_in[5];
    const float* W0   = (const float*)d_in[6];
    const float* b0   = (const float*)d_in[7];
    const float* W1   = (const float*)d_in[8];
    const float* b1   = (const float*)d_in[9];
    const float* Wo   = (const float*)d_in[10];
    const float* bo   = (const float*)d_in[11];
    float* out = (float*)d_out;

    decoder_fused_kernel<<<NPTS / TPB, TPB>>>(p, c, Cm, fpW, fpb, W0, b0, W1, b1, Wo, bo, out);
}

// round 2
// speedup vs baseline: 3.0276x; 3.0276x over previous
#include <cuda_runtime.h>

#define NPTS   65536     // B*T
#define TPB    256
#define PPB    (TPB/4)   // 64 points per block, 4 lanes per point

__global__ __launch_bounds__(TPB, 3)
void decoder_fused_kernel(
    const float* __restrict__ p,      // [16,4096,3]
    const float* __restrict__ c,      // [16,4,128,128,32]
    const float* __restrict__ Cmat,   // [16,4,4,3]
    const float* __restrict__ fcpW,   // [3,32]
    const float* __restrict__ fcpb,   // [32]
    const float* __restrict__ W0,     // [5,32,32]
    const float* __restrict__ b0,     // [5,32]
    const float* __restrict__ W1,     // [5,32,32]
    const float* __restrict__ b1,     // [5,32]
    const float* __restrict__ Wout,   // [32,1]
    const float* __restrict__ bout,   // [1]
    float* __restrict__ out)          // [16,4096]
{
    __shared__ __align__(16) float sW0[5 * 1024];
    __shared__ __align__(16) float sW1[5 * 1024];
    __shared__ __align__(16) float sb0[5 * 32];
    __shared__ __align__(16) float sb1[5 * 32];
    __shared__ __align__(16) float sWp[96];
    __shared__ __align__(16) float sbp[32];
    __shared__ __align__(16) float sWo[32];
    __shared__ float sbo;
    __shared__ float sC[4][8];   // per view: c00,c01,c02,c10,c11,c12,den

    const int tid = threadIdx.x;
    const int q4  = tid & 3;                      // channel quarter: owns ch [q4*8, q4*8+8)
    const int pt  = blockIdx.x * PPB + (tid >> 2);
    const int b   = pt >> 12;                     // 4096 pts per batch; block never spans two b

    // ---- stage weights in shared ----
    for (int i = tid; i < 5120; i += TPB) { sW0[i] = W0[i]; sW1[i] = W1[i]; }
    if (tid < 160) { sb0[tid] = b0[tid]; sb1[tid] = b1[tid]; }
    if (tid < 96) sWp[tid] = fcpW[tid];
    if (tid < 32) { sbp[tid] = fcpb[tid]; sWo[tid] = Wout[tid]; }
    if (tid == 0) sbo = bout[0];
    if (tid < 28) {
        int l = tid / 7, k = tid % 7;
        const float* Cb = Cmat + (b * 4 + l) * 12;   // [4,3] per (b,l)
        sC[l][k] = (k < 6) ? Cb[k] : (Cb[9] + 0.05f);
    }
    __syncthreads();

    // ---- load point (all 4 lanes of the group redundantly; L1 broadcast) ----
    const float pr0 = p[pt * 3 + 0];
    const float pr1 = p[pt * 3 + 1];
    const float pr2 = p[pt * 3 + 2];
    const float ps0 = pr0 / 0.55f;
    const float ps1 = pr1 / 0.55f;
    const float ps2 = pr2 / 0.55f;

    // ---- bilinear gather over 4 views -> cf[8] (this lane's 8 channels) ----
    float cf[8];
    #pragma unroll
    for (int j = 0; j < 8; j++) cf[j] = 0.0f;

    const float interval = 2.0f / 127.0f;

    #pragma unroll
    for (int l = 0; l < 4; l++) {
        const float c00 = sC[l][0], c01 = sC[l][1], c02 = sC[l][2];
        const float c10 = sC[l][3], c11 = sC[l][4], c12 = sC[l][5];
        const float den = sC[l][6];

        float px = (c00 * ps0 + c01 * ps1 + c02 * ps2) / den;
        float py = (c10 * ps0 + c11 * ps1 + c12 * ps2) / den;

        float xg = (px + 1.0f) / interval;
        float yg = (py + 1.0f) / interval;
        // match ref: first >=127 -> 126.9, then <0 -> 0
        xg = (xg >= 127.0f) ? 126.9f : xg;  xg = (xg < 0.0f) ? 0.0f : xg;
        yg = (yg >= 127.0f) ? 126.9f : yg;  yg = (yg < 0.0f) ? 0.0f : yg;

        // half-to-even rounding, same as jnp.round
        const float xl = rintf(xg - 0.5f), xr = rintf(xg + 0.5f);
        const float yl = rintf(yg - 0.5f), yh = rintf(yg + 0.5f);
        const int xil = (int)xl, xir = (int)xr;
        const int yil = (int)yl, yih = (int)yh;

        const float dx = xr - xg, dy = yh - yg;
        const float w11 = dx * dy;
        const float w12 = (1.0f - dx) * dy;
        const float w21 = dx * (1.0f - dy);
        const float w22 = (1.0f - dx) * (1.0f - dy);

        const int base = (b * 4 + l) * 128 * 128;     // plane row index
        // each lane reads its own 32B (2 x float4) slice of each 128B corner row:
        // the 4 lanes of a point cover contiguous 4x32B of the same line -> good coalescing
        const float4* r11 = (const float4*)(c + (size_t)(base + xil * 128 + yil) * 32) + q4 * 2;
        const float4* r12 = (const float4*)(c + (size_t)(base + xir * 128 + yil) * 32) + q4 * 2;
        const float4* r21 = (const float4*)(c + (size_t)(base + xil * 128 + yih) * 32) + q4 * 2;
        const float4* r22 = (const float4*)(c + (size_t)(base + xir * 128 + yih) * 32) + q4 * 2;

        #pragma unroll
        for (int q = 0; q < 2; q++) {
            const float4 a = __ldg(r11 + q);
            const float4 e = __ldg(r12 + q);
            const float4 f = __ldg(r21 + q);
            const float4 g = __ldg(r22 + q);
            cf[4*q + 0] += w11 * a.x + w12 * e.x + w21 * f.x + w22 * g.x;
            cf[4*q + 1] += w11 * a.y + w12 * e.y + w21 * f.y + w22 * g.y;
            cf[4*q + 2] += w11 * a.z + w12 * e.z + w21 * f.z + w22 * g.z;
            cf[4*q + 3] += w11 * a.w + w12 * e.w + w21 * f.w + w22 * g.w;
        }
    }

    // ---- fc_p + first cf add (this lane's 8 output channels) ----
    const int chb = q4 * 8;
    float x[8];
    #pragma unroll
    for (int j = 0; j < 8; j++) {
        const int ch = chb + j;
        float v = sbp[ch];
        v = fmaf(pr0, sWp[ch],      v);
        v = fmaf(pr1, sWp[32 + ch], v);
        v = fmaf(pr2, sWp[64 + ch], v);
        x[j] = v + cf[j];
    }

    const unsigned FULL = 0xffffffffu;

    // ---- 5 resnet blocks ----
    #pragma unroll 1
    for (int blk = 0; blk < 5; blk++) {
        if (blk > 0) {
            #pragma unroll
            for (int j = 0; j < 8; j++) x[j] += cf[j];
        }
        const float* w0base = sW0 + blk * 1024 + chb;  // column slice for this lane
        const float* w1base = sW1 + blk * 1024 + chb;

        // h = relu(x) @ W0 + b0   (h holds this lane's 8 channels)
        float h[8];
        #pragma unroll
        for (int j = 0; j < 8; j++) h[j] = sb0[blk * 32 + chb + j];

        #pragma unroll
        for (int kk = 0; kk < 8; kk++) {
            // broadcast x[global k = qq*8+kk] from each quarter-owner lane
            const float v0 = fmaxf(__shfl_sync(FULL, x[kk], 0, 4), 0.0f);
            const float v1 = fmaxf(__shfl_sync(FULL, x[kk], 1, 4), 0.0f);
            const float v2 = fmaxf(__shfl_sync(FULL, x[kk], 2, 4), 0.0f);
            const float v3 = fmaxf(__shfl_sync(FULL, x[kk], 3, 4), 0.0f);

            const float4* r0 = (const float4*)(w0base + (kk     ) * 32);
            const float4* r1 = (const float4*)(w0base + (kk +  8) * 32);
            const float4* r2 = (const float4*)(w0base + (kk + 16) * 32);
            const float4* r3 = (const float4*)(w0base + (kk + 24) * 32);
            #pragma unroll
            for (int q = 0; q < 2; q++) {
                const float4 a = r0[q], e = r1[q], f = r2[q], g = r3[q];
                h[4*q + 0] = fmaf(v0, a.x, fmaf(v1, e.x, fmaf(v2, f.x, fmaf(v3, g.x, h[4*q + 0]))));
                h[4*q + 1] = fmaf(v0, a.y, fmaf(v1, e.y, fmaf(v2, f.y, fmaf(v3, g.y, h[4*q + 1]))));
                h[4*q + 2] = fmaf(v0, a.z, fmaf(v1, e.z, fmaf(v2, f.z, fmaf(v3, g.z, h[4*q + 2]))));
                h[4*q + 3] = fmaf(v0, a.w, fmaf(v1, e.w, fmaf(v2, f.w, fmaf(v3, g.w, h[4*q + 3]))));
            }
        }

        // x += relu(h) @ W1 + b1
        #pragma unroll
        for (int j = 0; j < 8; j++) x[j] += sb1[blk * 32 + chb + j];

        #pragma unroll
        for (int kk = 0; kk < 8; kk++) {
            const float v0 = fmaxf(__shfl_sync(FULL, h[kk], 0, 4), 0.0f);
            const float v1 = fmaxf(__shfl_sync(FULL, h[kk], 1, 4), 0.0f);
            const float v2 = fmaxf(__shfl_sync(FULL, h[kk], 2, 4), 0.0f);
            const float v3 = fmaxf(__shfl_sync(FULL, h[kk], 3, 4), 0.0f);

            const float4* r0 = (const float4*)(w1base + (kk     ) * 32);
            const float4* r1 = (const float4*)(w1base + (kk +  8) * 32);
            const float4* r2 = (const float4*)(w1base + (kk + 16) * 32);
            const float4* r3 = (const float4*)(w1base + (kk + 24) * 32);
            #pragma unroll
            for (int q = 0; q < 2; q++) {
                const float4 a = r0[q], e = r1[q], f = r2[q], g = r3[q];
                x[4*q + 0] = fmaf(v0, a.x, fmaf(v1, e.x, fmaf(v2, f.x, fmaf(v3, g.x, x[4*q + 0]))));
                x[4*q + 1] = fmaf(v0, a.y, fmaf(v1, e.y, fmaf(v2, f.y, fmaf(v3, g.y, x[4*q + 1]))));
                x[4*q + 2] = fmaf(v0, a.z, fmaf(v1, e.z, fmaf(v2, f.z, fmaf(v3, g.z, x[4*q + 2]))));
                x[4*q + 3] = fmaf(v0, a.w, fmaf(v1, e.w, fmaf(v2, f.w, fmaf(v3, g.w, x[4*q + 3]))));
            }
        }
    }

    // ---- output head: partial dot over this lane's 8 channels, reduce over 4 lanes ----
    float acc = 0.0f;
    #pragma unroll
    for (int j = 0; j < 8; j++)
        acc = fmaf(fmaxf(x[j], 0.0f), sWo[chb + j], acc);
    acc += __shfl_xor_sync(FULL, acc, 1);
    acc += __shfl_xor_sync(FULL, acc, 2);
    if (q4 == 0) out[pt] = acc + sbo;
}

extern "C" void kernel_launch(void* const* d_in, const int* in_sizes, int n_in,
                              void* d_out, int out_size)
{
    // metadata order: p, z, c, C_mat, fc_p_W, fc_p_b,
    //                 blocks_W0, blocks_b0, blocks_W1, blocks_b1, fc_out_W, fc_out_b
    const float* p    = (const float*)d_in[0];
    // d_in[1] = z (unused by the reference graph)
    const float* c    = (const float*)d_in[2];
    const float* Cm   = (const float*)d_in[3];
    const float* fpW  = (const float*)d_in[4];
    const float* fpb  = (const float*)d_in[5];
    const float* W0   = (const float*)d_in[6];
    const float* b0   = (const float*)d_in[7];
    const float* W1   = (const float*)d_in[8];
    const float* b1   = (const float*)d_in[9];
    const float* Wo   = (const float*)d_in[10];
    const float* bo   = (const float*)d_in[11];
    float* out = (float*)d_out;

    decoder_fused_kernel<<<NPTS / PPB, TPB>>>(p, c, Cm, fpW, fpb, W0, b0, W1, b1, Wo, bo, out);
}